// round 11
// baseline (speedup 1.0000x reference)
#include <cuda_runtime.h>
#include <cuda_fp16.h>
#include <math.h>
#include <stdint.h>

#define BATCH 2
#define SEQ   2048
#define NH    16
#define HD    64
#define HID   1024            // NH*HD
#define MROWS (BATCH*SEQ)     // 4096

// Scratch (no allocations allowed)
__device__ float g_q[MROWS * HID];
__device__ float g_k[MROWS * HID];
__device__ float g_v[MROWS * HID];
__device__ float g_cos[SEQ * 32];
__device__ float g_sin[SEQ * 32];

__device__ __forceinline__ void mma_f16(float c[4], const uint32_t a[4],
                                        uint32_t b0, uint32_t b1) {
    asm volatile(
        "mma.sync.aligned.m16n8k16.row.col.f32.f16.f16.f32 "
        "{%0,%1,%2,%3},{%4,%5,%6,%7},{%8,%9},{%0,%1,%2,%3};"
        : "+f"(c[0]), "+f"(c[1]), "+f"(c[2]), "+f"(c[3])
        : "r"(a[0]), "r"(a[1]), "r"(a[2]), "r"(a[3]), "r"(b0), "r"(b1));
}

__device__ __forceinline__ uint32_t packh2(float lo, float hi) {
    __half2 h = __floats2half2_rn(lo, hi);
    return *(uint32_t*)&h;
}

// Bank-spread swizzle key for [row][pair] half2 layouts (32 words/row).
__device__ __forceinline__ int FSW(int d) { return ((d & 7) << 2) | ((d >> 3) & 3); }

// ---------------------------------------------------------------------------
// QKV projection, fp16 m16n8k16: Y = X @ W^T.
// X[M,K] row-major, W[N,K] row-major. blockIdx.z selects q/k/v.
// Block tile 128x128, K-step 32. 8 warps in 4x2 (warp tile 32x64).
// SMEM: half2 words, 16 pairs/row padded to 20 (bank stride 20 => rows 0..7
// of any g-lane group land in distinct banks; no XOR math needed).
// ---------------------------------------------------------------------------
#define QPAD 20
__global__ __launch_bounds__(256)
void qkv_gemm(const float* __restrict__ X,
              const float* __restrict__ Wq,
              const float* __restrict__ Wk,
              const float* __restrict__ Wv) {
    __shared__ uint32_t As2[128 * QPAD];
    __shared__ uint32_t Bs2[128 * QPAD];

    const float* W = (blockIdx.z == 0) ? Wq : (blockIdx.z == 1) ? Wk : Wv;
    float* Y       = (blockIdx.z == 0) ? g_q : (blockIdx.z == 1) ? g_k : g_v;

    const int m0 = blockIdx.y * 128;
    const int n0 = blockIdx.x * 128;
    const int tid  = threadIdx.x;
    const int warp = tid >> 5;
    const int lane = tid & 31;
    const int g = lane >> 2;
    const int t = lane & 3;
    const int wm0 = (warp >> 1) * 32;   // 0,32,64,96
    const int wn0 = (warp & 1) * 64;    // 0,64

    float acc[2][8][4];
#pragma unroll
    for (int mt = 0; mt < 2; mt++)
#pragma unroll
        for (int nt = 0; nt < 8; nt++)
#pragma unroll
            for (int e = 0; e < 4; e++) acc[mt][nt][e] = 0.0f;

    for (int k0 = 0; k0 < HID; k0 += 32) {
        // Stage A and B tiles: 128 rows x 32 cols fp32 -> half2 pairs
#pragma unroll
        for (int u = 0; u < 4; u++) {
            int idx = tid + u * 256;
            int row = idx >> 3;          // 0..127
            int c4  = (idx & 7) * 4;     // 0..28
            int w0  = row * QPAD + (c4 >> 1);
            float4 xa = *(const float4*)&X[(size_t)(m0 + row) * HID + k0 + c4];
            As2[w0]     = packh2(xa.x, xa.y);
            As2[w0 + 1] = packh2(xa.z, xa.w);
            float4 wb = *(const float4*)&W[(size_t)(n0 + row) * HID + k0 + c4];
            Bs2[w0]     = packh2(wb.x, wb.y);
            Bs2[w0 + 1] = packh2(wb.z, wb.w);
        }
        __syncthreads();

#pragma unroll
        for (int kb = 0; kb < 2; kb++) {
            uint32_t a[2][4];
#pragma unroll
            for (int mt = 0; mt < 2; mt++) {
                int ra = (wm0 + mt * 16 + g) * QPAD;
                int rb = (wm0 + mt * 16 + 8 + g) * QPAD;
                a[mt][0] = As2[ra + kb * 8 + t];
                a[mt][1] = As2[rb + kb * 8 + t];
                a[mt][2] = As2[ra + kb * 8 + 4 + t];
                a[mt][3] = As2[rb + kb * 8 + 4 + t];
            }
#pragma unroll
            for (int nt = 0; nt < 8; nt++) {
                int rc = (wn0 + nt * 8 + g) * QPAD;
                uint32_t b0 = Bs2[rc + kb * 8 + t];
                uint32_t b1 = Bs2[rc + kb * 8 + 4 + t];
                mma_f16(acc[0][nt], a[0], b0, b1);
                mma_f16(acc[1][nt], a[1], b0, b1);
            }
        }
        __syncthreads();
    }

#pragma unroll
    for (int mt = 0; mt < 2; mt++)
#pragma unroll
        for (int nt = 0; nt < 8; nt++) {
            int row0 = m0 + wm0 + mt * 16 + g;
            int col  = n0 + wn0 + nt * 8 + 2 * t;
            *(float2*)&Y[(size_t)row0 * HID + col] =
                make_float2(acc[mt][nt][0], acc[mt][nt][1]);
            *(float2*)&Y[(size_t)(row0 + 8) * HID + col] =
                make_float2(acc[mt][nt][2], acc[mt][nt][3]);
        }
}

// ---------------------------------------------------------------------------
// RoPE tables (apply is fused into attention staging)
// ---------------------------------------------------------------------------
__global__ void rope_table() {
    int idx = blockIdx.x * blockDim.x + threadIdx.x;
    if (idx >= SEQ * 32) return;
    int s = idx >> 5;
    int j = idx & 31;
    double inv = pow(10000.0, -(double)j / 32.0);
    double a = (double)s * inv;
    g_cos[idx] = (float)cos(a);
    g_sin[idx] = (float)sin(a);
}

// ---------------------------------------------------------------------------
// Flash attention, fp16 m16n8k16 (unchanged from round 6 — known good).
// ---------------------------------------------------------------------------
__global__ __launch_bounds__(128)
void attn_kernel(float* __restrict__ out) {
    __shared__ uint32_t sh[4096];     // 16 KB
    uint32_t* Kh = sh;                // 2048 words
    uint32_t* Vh = sh + 2048;         // 2048 words

    const int tid  = threadIdx.x;
    const int warp = tid >> 5;
    const int lane = tid & 31;
    const int g = lane >> 2;
    const int t = lane & 3;
    const int h = blockIdx.y & (NH - 1);
    const int b = blockIdx.y >> 4;
    const int q0 = blockIdx.x * 128;

    const float* qptr = g_q + (size_t)b * SEQ * HID + h * HD;
    const float* kptr = g_k + (size_t)b * SEQ * HID + h * HD;
    const float* vptr = g_v + (size_t)b * SEQ * HID + h * HD;

    // ---- Stage Q (RoPE + 1/8 scale) into this warp's scratch, grab frags ----
    uint32_t* Qs = sh + warp * 1024;  // 32 rows x 32 words
#pragma unroll
    for (int it = 0; it < 8; it++) {
        int idx2 = lane + it * 32;
        int dg = idx2 & 7;
        int r  = idx2 >> 3;
        int row = q0 + warp * 32 + r;
        const float* qr = qptr + (size_t)row * HID;
        float4 lo = *(const float4*)&qr[dg * 4];
        float4 hi = *(const float4*)&qr[dg * 4 + 32];
        float4 cz = *(const float4*)&g_cos[row * 32 + dg * 4];
        float4 sz = *(const float4*)&g_sin[row * 32 + dg * 4];
        float a0 = (lo.x * cz.x - hi.x * sz.x) * 0.125f;
        float a1 = (lo.y * cz.y - hi.y * sz.y) * 0.125f;
        float a2 = (lo.z * cz.z - hi.z * sz.z) * 0.125f;
        float a3 = (lo.w * cz.w - hi.w * sz.w) * 0.125f;
        float b0 = (hi.x * cz.x + lo.x * sz.x) * 0.125f;
        float b1 = (hi.y * cz.y + lo.y * sz.y) * 0.125f;
        float b2 = (hi.z * cz.z + lo.z * sz.z) * 0.125f;
        float b3 = (hi.w * cz.w + lo.w * sz.w) * 0.125f;
        int fr = FSW(r);
        Qs[r * 32 + ((dg * 2 + 0)  ^ fr)] = packh2(a0, a1);
        Qs[r * 32 + ((dg * 2 + 1)  ^ fr)] = packh2(a2, a3);
        Qs[r * 32 + ((dg * 2 + 16) ^ fr)] = packh2(b0, b1);
        Qs[r * 32 + ((dg * 2 + 17) ^ fr)] = packh2(b2, b3);
    }
    __syncwarp();
    uint32_t qa[2][4][4];
#pragma unroll
    for (int mt = 0; mt < 2; mt++) {
        int ra = mt * 16 + g, rb = mt * 16 + 8 + g;
        int fa = FSW(ra), fb = FSW(rb);
#pragma unroll
        for (int kb = 0; kb < 4; kb++) {
            qa[mt][kb][0] = Qs[ra * 32 + ((kb * 8 + t)     ^ fa)];
            qa[mt][kb][1] = Qs[rb * 32 + ((kb * 8 + t)     ^ fb)];
            qa[mt][kb][2] = Qs[ra * 32 + ((kb * 8 + t + 4) ^ fa)];
            qa[mt][kb][3] = Qs[rb * 32 + ((kb * 8 + t + 4) ^ fb)];
        }
    }

    float m_i[2][2], l_i[2][2];
    float o[2][8][4];
#pragma unroll
    for (int mt = 0; mt < 2; mt++) {
        m_i[mt][0] = m_i[mt][1] = -1e30f;
        l_i[mt][0] = l_i[mt][1] = 0.0f;
#pragma unroll
        for (int nb = 0; nb < 8; nb++)
#pragma unroll
            for (int e = 0; e < 4; e++) o[mt][nb][e] = 0.0f;
    }

    for (int k0 = 0; k0 < SEQ; k0 += 64) {
        __syncthreads();

        // ---- Stage K (with RoPE) ----
#pragma unroll
        for (int u = 0; u < 4; u++) {
            int idx = tid + u * 128;
            int dg = idx & 7;
            int r  = idx >> 3;
            int pos = k0 + r;
            const float* kr = kptr + (size_t)pos * HID;
            float4 lo = *(const float4*)&kr[dg * 4];
            float4 hi = *(const float4*)&kr[dg * 4 + 32];
            float4 cz = *(const float4*)&g_cos[pos * 32 + dg * 4];
            float4 sz = *(const float4*)&g_sin[pos * 32 + dg * 4];
            int fr = FSW(r);
            Kh[r * 32 + ((dg * 2 + 0)  ^ fr)] =
                packh2(lo.x * cz.x - hi.x * sz.x, lo.y * cz.y - hi.y * sz.y);
            Kh[r * 32 + ((dg * 2 + 1)  ^ fr)] =
                packh2(lo.z * cz.z - hi.z * sz.z, lo.w * cz.w - hi.w * sz.w);
            Kh[r * 32 + ((dg * 2 + 16) ^ fr)] =
                packh2(hi.x * cz.x + lo.x * sz.x, hi.y * cz.y + lo.y * sz.y);
            Kh[r * 32 + ((dg * 2 + 17) ^ fr)] =
                packh2(hi.z * cz.z + lo.z * sz.z, hi.w * cz.w + lo.w * sz.w);
        }
        // ---- Stage V (transposed: [dim][keypair]) ----
#pragma unroll
        for (int u = 0; u < 4; u++) {
            int idx = tid + u * 128;
            int c4 = (idx & 15) * 4;
            int kp = idx >> 4;
            const float* v0 = vptr + (size_t)(k0 + 2 * kp) * HID;
            float4 va = *(const float4*)&v0[c4];
            float4 vb = *(const float4*)&v0[HID + c4];
            Vh[(c4 + 0) * 32 + (kp ^ FSW(c4 + 0))] = packh2(va.x, vb.x);
            Vh[(c4 + 1) * 32 + (kp ^ FSW(c4 + 1))] = packh2(va.y, vb.y);
            Vh[(c4 + 2) * 32 + (kp ^ FSW(c4 + 2))] = packh2(va.z, vb.z);
            Vh[(c4 + 3) * 32 + (kp ^ FSW(c4 + 3))] = packh2(va.w, vb.w);
        }
        __syncthreads();

        // ---- S = Q @ K^T : 32x64 per warp ----
        float s[2][8][4];
#pragma unroll
        for (int mt = 0; mt < 2; mt++)
#pragma unroll
            for (int nb = 0; nb < 8; nb++)
#pragma unroll
                for (int e = 0; e < 4; e++) s[mt][nb][e] = 0.0f;

#pragma unroll
        for (int kb = 0; kb < 4; kb++) {
#pragma unroll
            for (int nb = 0; nb < 8; nb++) {
                int key = nb * 8 + g;
                int fk = FSW(key);
                uint32_t b0 = Kh[key * 32 + ((kb * 8 + t)     ^ fk)];
                uint32_t b1 = Kh[key * 32 + ((kb * 8 + t + 4) ^ fk)];
                mma_f16(s[0][nb], qa[0][kb], b0, b1);
                mma_f16(s[1][nb], qa[1][kb], b0, b1);
            }
        }

        // ---- Online softmax; pack P into fp16 A-frags (registers only) ----
        uint32_t pa[2][4][4];
#pragma unroll
        for (int mt = 0; mt < 2; mt++) {
#pragma unroll
            for (int hh = 0; hh < 2; hh++) {
                const int e0 = hh * 2;
                float mx = -1e30f;
#pragma unroll
                for (int nb = 0; nb < 8; nb++)
                    mx = fmaxf(mx, fmaxf(s[mt][nb][e0], s[mt][nb][e0 + 1]));
                mx = fmaxf(mx, __shfl_xor_sync(0xffffffffu, mx, 1));
                mx = fmaxf(mx, __shfl_xor_sync(0xffffffffu, mx, 2));
                float mnew = fmaxf(m_i[mt][hh], mx);
                float corr = __expf(m_i[mt][hh] - mnew);
                float rs = 0.0f;
#pragma unroll
                for (int nb = 0; nb < 8; nb++) {
                    float p0 = __expf(s[mt][nb][e0]     - mnew);
                    float p1 = __expf(s[mt][nb][e0 + 1] - mnew);
                    rs += p0 + p1;
                    s[mt][nb][e0]     = p0;
                    s[mt][nb][e0 + 1] = p1;
                }
                rs += __shfl_xor_sync(0xffffffffu, rs, 1);
                rs += __shfl_xor_sync(0xffffffffu, rs, 2);
                l_i[mt][hh] = l_i[mt][hh] * corr + rs;
                m_i[mt][hh] = mnew;
#pragma unroll
                for (int nb = 0; nb < 8; nb++) {
                    o[mt][nb][e0]     *= corr;
                    o[mt][nb][e0 + 1] *= corr;
                }
            }
#pragma unroll
            for (int kb = 0; kb < 4; kb++) {
                pa[mt][kb][0] = packh2(s[mt][2 * kb][0],     s[mt][2 * kb][1]);
                pa[mt][kb][1] = packh2(s[mt][2 * kb][2],     s[mt][2 * kb][3]);
                pa[mt][kb][2] = packh2(s[mt][2 * kb + 1][0], s[mt][2 * kb + 1][1]);
                pa[mt][kb][3] = packh2(s[mt][2 * kb + 1][2], s[mt][2 * kb + 1][3]);
            }
        }

        // ---- ctx += P @ V : 32x64 per warp ----
#pragma unroll
        for (int kb = 0; kb < 4; kb++) {
#pragma unroll
            for (int nb = 0; nb < 8; nb++) {
                int dim = nb * 8 + g;
                int fd = FSW(dim);
                uint32_t b0 = Vh[dim * 32 + ((kb * 8 + t)     ^ fd)];
                uint32_t b1 = Vh[dim * 32 + ((kb * 8 + t + 4) ^ fd)];
                mma_f16(o[0][nb], pa[0][kb], b0, b1);
                mma_f16(o[1][nb], pa[1][kb], b0, b1);
            }
        }
    }

    // ---- Normalize and write out[b, s, h*64 + d] ----
#pragma unroll
    for (int mt = 0; mt < 2; mt++)
#pragma unroll
        for (int hh = 0; hh < 2; hh++) {
            float inv_l = 1.0f / l_i[mt][hh];
            int row = q0 + warp * 32 + mt * 16 + g + 8 * hh;
#pragma unroll
            for (int nb = 0; nb < 8; nb++) {
                size_t base = (size_t)(b * SEQ + row) * HID + h * HD + nb * 8 + 2 * t;
                *(float2*)&out[base] = make_float2(o[mt][nb][2 * hh]     * inv_l,
                                                   o[mt][nb][2 * hh + 1] * inv_l);
            }
        }
}

// ---------------------------------------------------------------------------
extern "C" void kernel_launch(void* const* d_in, const int* in_sizes, int n_in,
                              void* d_out, int out_size) {
    const float* X  = (const float*)d_in[0];
    const float* Wq = (const float*)d_in[1];
    const float* Wk = (const float*)d_in[2];
    const float* Wv = (const float*)d_in[3];
    float* out = (float*)d_out;

    qkv_gemm<<<dim3(HID / 128, MROWS / 128, 3), 256>>>(X, Wq, Wk, Wv);
    rope_table<<<(SEQ * 32 + 255) / 256, 256>>>();
    attn_kernel<<<dim3(SEQ / 128, NH * BATCH), 128>>>(out);
}

// round 12
// speedup vs baseline: 1.0017x; 1.0017x over previous
#include <cuda_runtime.h>
#include <cuda_fp16.h>
#include <math.h>
#include <stdint.h>

#define BATCH 2
#define SEQ   2048
#define NH    16
#define HD    64
#define HID   1024            // NH*HD
#define MROWS (BATCH*SEQ)     // 4096

// Scratch (no allocations allowed)
__device__ float g_q[MROWS * HID];
__device__ float g_k[MROWS * HID];
__device__ float g_v[MROWS * HID];
__device__ float g_cos[SEQ * 32];
__device__ float g_sin[SEQ * 32];

__device__ __forceinline__ void mma_f16(float c[4], const uint32_t a[4],
                                        uint32_t b0, uint32_t b1) {
    asm volatile(
        "mma.sync.aligned.m16n8k16.row.col.f32.f16.f16.f32 "
        "{%0,%1,%2,%3},{%4,%5,%6,%7},{%8,%9},{%0,%1,%2,%3};"
        : "+f"(c[0]), "+f"(c[1]), "+f"(c[2]), "+f"(c[3])
        : "r"(a[0]), "r"(a[1]), "r"(a[2]), "r"(a[3]), "r"(b0), "r"(b1));
}

__device__ __forceinline__ uint32_t packh2(float lo, float hi) {
    __half2 h = __floats2half2_rn(lo, hi);
    return *(uint32_t*)&h;
}

// Bank-spread swizzle key for [row][pair] half2 layouts (32 words/row).
__device__ __forceinline__ int FSW(int d) { return ((d & 7) << 2) | ((d >> 3) & 3); }

// ---------------------------------------------------------------------------
// QKV projection, fp16 m16n8k16: Y = X @ W^T.
// X[M,K] row-major, W[N,K] row-major. blockIdx.z selects q/k/v.
// Block tile 128x128, K-step 32. 8 warps in 4x2 (warp tile 32x64).
// SMEM: half2 words, 16 pairs/row padded to 20 (bank stride 20 => rows 0..7
// of any g-lane group land in distinct banks; no XOR math needed).
// ---------------------------------------------------------------------------
#define QPAD 20
__global__ __launch_bounds__(256)
void qkv_gemm(const float* __restrict__ X,
              const float* __restrict__ Wq,
              const float* __restrict__ Wk,
              const float* __restrict__ Wv) {
    __shared__ uint32_t As2[128 * QPAD];
    __shared__ uint32_t Bs2[128 * QPAD];

    const float* W = (blockIdx.z == 0) ? Wq : (blockIdx.z == 1) ? Wk : Wv;
    float* Y       = (blockIdx.z == 0) ? g_q : (blockIdx.z == 1) ? g_k : g_v;

    const int m0 = blockIdx.y * 128;
    const int n0 = blockIdx.x * 128;
    const int tid  = threadIdx.x;
    const int warp = tid >> 5;
    const int lane = tid & 31;
    const int g = lane >> 2;
    const int t = lane & 3;
    const int wm0 = (warp >> 1) * 32;   // 0,32,64,96
    const int wn0 = (warp & 1) * 64;    // 0,64

    float acc[2][8][4];
#pragma unroll
    for (int mt = 0; mt < 2; mt++)
#pragma unroll
        for (int nt = 0; nt < 8; nt++)
#pragma unroll
            for (int e = 0; e < 4; e++) acc[mt][nt][e] = 0.0f;

    for (int k0 = 0; k0 < HID; k0 += 32) {
        // Stage A and B tiles: 128 rows x 32 cols fp32 -> half2 pairs
#pragma unroll
        for (int u = 0; u < 4; u++) {
            int idx = tid + u * 256;
            int row = idx >> 3;          // 0..127
            int c4  = (idx & 7) * 4;     // 0..28
            int w0  = row * QPAD + (c4 >> 1);
            float4 xa = *(const float4*)&X[(size_t)(m0 + row) * HID + k0 + c4];
            As2[w0]     = packh2(xa.x, xa.y);
            As2[w0 + 1] = packh2(xa.z, xa.w);
            float4 wb = *(const float4*)&W[(size_t)(n0 + row) * HID + k0 + c4];
            Bs2[w0]     = packh2(wb.x, wb.y);
            Bs2[w0 + 1] = packh2(wb.z, wb.w);
        }
        __syncthreads();

#pragma unroll
        for (int kb = 0; kb < 2; kb++) {
            uint32_t a[2][4];
#pragma unroll
            for (int mt = 0; mt < 2; mt++) {
                int ra = (wm0 + mt * 16 + g) * QPAD;
                int rb = (wm0 + mt * 16 + 8 + g) * QPAD;
                a[mt][0] = As2[ra + kb * 8 + t];
                a[mt][1] = As2[rb + kb * 8 + t];
                a[mt][2] = As2[ra + kb * 8 + 4 + t];
                a[mt][3] = As2[rb + kb * 8 + 4 + t];
            }
#pragma unroll
            for (int nt = 0; nt < 8; nt++) {
                int rc = (wn0 + nt * 8 + g) * QPAD;
                uint32_t b0 = Bs2[rc + kb * 8 + t];
                uint32_t b1 = Bs2[rc + kb * 8 + 4 + t];
                mma_f16(acc[0][nt], a[0], b0, b1);
                mma_f16(acc[1][nt], a[1], b0, b1);
            }
        }
        __syncthreads();
    }

#pragma unroll
    for (int mt = 0; mt < 2; mt++)
#pragma unroll
        for (int nt = 0; nt < 8; nt++) {
            int row0 = m0 + wm0 + mt * 16 + g;
            int col  = n0 + wn0 + nt * 8 + 2 * t;
            *(float2*)&Y[(size_t)row0 * HID + col] =
                make_float2(acc[mt][nt][0], acc[mt][nt][1]);
            *(float2*)&Y[(size_t)(row0 + 8) * HID + col] =
                make_float2(acc[mt][nt][2], acc[mt][nt][3]);
        }
}

// ---------------------------------------------------------------------------
// RoPE tables (apply is fused into attention staging)
// ---------------------------------------------------------------------------
__global__ void rope_table() {
    int idx = blockIdx.x * blockDim.x + threadIdx.x;
    if (idx >= SEQ * 32) return;
    int s = idx >> 5;
    int j = idx & 31;
    double inv = pow(10000.0, -(double)j / 32.0);
    double a = (double)s * inv;
    g_cos[idx] = (float)cos(a);
    g_sin[idx] = (float)sin(a);
}

// ---------------------------------------------------------------------------
// Flash attention, fp16 m16n8k16 (unchanged from round 6 — known good).
// ---------------------------------------------------------------------------
__global__ __launch_bounds__(128)
void attn_kernel(float* __restrict__ out) {
    __shared__ uint32_t sh[4096];     // 16 KB
    uint32_t* Kh = sh;                // 2048 words
    uint32_t* Vh = sh + 2048;         // 2048 words

    const int tid  = threadIdx.x;
    const int warp = tid >> 5;
    const int lane = tid & 31;
    const int g = lane >> 2;
    const int t = lane & 3;
    const int h = blockIdx.y & (NH - 1);
    const int b = blockIdx.y >> 4;
    const int q0 = blockIdx.x * 128;

    const float* qptr = g_q + (size_t)b * SEQ * HID + h * HD;
    const float* kptr = g_k + (size_t)b * SEQ * HID + h * HD;
    const float* vptr = g_v + (size_t)b * SEQ * HID + h * HD;

    // ---- Stage Q (RoPE + 1/8 scale) into this warp's scratch, grab frags ----
    uint32_t* Qs = sh + warp * 1024;  // 32 rows x 32 words
#pragma unroll
    for (int it = 0; it < 8; it++) {
        int idx2 = lane + it * 32;
        int dg = idx2 & 7;
        int r  = idx2 >> 3;
        int row = q0 + warp * 32 + r;
        const float* qr = qptr + (size_t)row * HID;
        float4 lo = *(const float4*)&qr[dg * 4];
        float4 hi = *(const float4*)&qr[dg * 4 + 32];
        float4 cz = *(const float4*)&g_cos[row * 32 + dg * 4];
        float4 sz = *(const float4*)&g_sin[row * 32 + dg * 4];
        float a0 = (lo.x * cz.x - hi.x * sz.x) * 0.125f;
        float a1 = (lo.y * cz.y - hi.y * sz.y) * 0.125f;
        float a2 = (lo.z * cz.z - hi.z * sz.z) * 0.125f;
        float a3 = (lo.w * cz.w - hi.w * sz.w) * 0.125f;
        float b0 = (hi.x * cz.x + lo.x * sz.x) * 0.125f;
        float b1 = (hi.y * cz.y + lo.y * sz.y) * 0.125f;
        float b2 = (hi.z * cz.z + lo.z * sz.z) * 0.125f;
        float b3 = (hi.w * cz.w + lo.w * sz.w) * 0.125f;
        int fr = FSW(r);
        Qs[r * 32 + ((dg * 2 + 0)  ^ fr)] = packh2(a0, a1);
        Qs[r * 32 + ((dg * 2 + 1)  ^ fr)] = packh2(a2, a3);
        Qs[r * 32 + ((dg * 2 + 16) ^ fr)] = packh2(b0, b1);
        Qs[r * 32 + ((dg * 2 + 17) ^ fr)] = packh2(b2, b3);
    }
    __syncwarp();
    uint32_t qa[2][4][4];
#pragma unroll
    for (int mt = 0; mt < 2; mt++) {
        int ra = mt * 16 + g, rb = mt * 16 + 8 + g;
        int fa = FSW(ra), fb = FSW(rb);
#pragma unroll
        for (int kb = 0; kb < 4; kb++) {
            qa[mt][kb][0] = Qs[ra * 32 + ((kb * 8 + t)     ^ fa)];
            qa[mt][kb][1] = Qs[rb * 32 + ((kb * 8 + t)     ^ fb)];
            qa[mt][kb][2] = Qs[ra * 32 + ((kb * 8 + t + 4) ^ fa)];
            qa[mt][kb][3] = Qs[rb * 32 + ((kb * 8 + t + 4) ^ fb)];
        }
    }

    float m_i[2][2], l_i[2][2];
    float o[2][8][4];
#pragma unroll
    for (int mt = 0; mt < 2; mt++) {
        m_i[mt][0] = m_i[mt][1] = -1e30f;
        l_i[mt][0] = l_i[mt][1] = 0.0f;
#pragma unroll
        for (int nb = 0; nb < 8; nb++)
#pragma unroll
            for (int e = 0; e < 4; e++) o[mt][nb][e] = 0.0f;
    }

    for (int k0 = 0; k0 < SEQ; k0 += 64) {
        __syncthreads();

        // ---- Stage K (with RoPE) ----
#pragma unroll
        for (int u = 0; u < 4; u++) {
            int idx = tid + u * 128;
            int dg = idx & 7;
            int r  = idx >> 3;
            int pos = k0 + r;
            const float* kr = kptr + (size_t)pos * HID;
            float4 lo = *(const float4*)&kr[dg * 4];
            float4 hi = *(const float4*)&kr[dg * 4 + 32];
            float4 cz = *(const float4*)&g_cos[pos * 32 + dg * 4];
            float4 sz = *(const float4*)&g_sin[pos * 32 + dg * 4];
            int fr = FSW(r);
            Kh[r * 32 + ((dg * 2 + 0)  ^ fr)] =
                packh2(lo.x * cz.x - hi.x * sz.x, lo.y * cz.y - hi.y * sz.y);
            Kh[r * 32 + ((dg * 2 + 1)  ^ fr)] =
                packh2(lo.z * cz.z - hi.z * sz.z, lo.w * cz.w - hi.w * sz.w);
            Kh[r * 32 + ((dg * 2 + 16) ^ fr)] =
                packh2(hi.x * cz.x + lo.x * sz.x, hi.y * cz.y + lo.y * sz.y);
            Kh[r * 32 + ((dg * 2 + 17) ^ fr)] =
                packh2(hi.z * cz.z + lo.z * sz.z, hi.w * cz.w + lo.w * sz.w);
        }
        // ---- Stage V (transposed: [dim][keypair]) ----
#pragma unroll
        for (int u = 0; u < 4; u++) {
            int idx = tid + u * 128;
            int c4 = (idx & 15) * 4;
            int kp = idx >> 4;
            const float* v0 = vptr + (size_t)(k0 + 2 * kp) * HID;
            float4 va = *(const float4*)&v0[c4];
            float4 vb = *(const float4*)&v0[HID + c4];
            Vh[(c4 + 0) * 32 + (kp ^ FSW(c4 + 0))] = packh2(va.x, vb.x);
            Vh[(c4 + 1) * 32 + (kp ^ FSW(c4 + 1))] = packh2(va.y, vb.y);
            Vh[(c4 + 2) * 32 + (kp ^ FSW(c4 + 2))] = packh2(va.z, vb.z);
            Vh[(c4 + 3) * 32 + (kp ^ FSW(c4 + 3))] = packh2(va.w, vb.w);
        }
        __syncthreads();

        // ---- S = Q @ K^T : 32x64 per warp ----
        float s[2][8][4];
#pragma unroll
        for (int mt = 0; mt < 2; mt++)
#pragma unroll
            for (int nb = 0; nb < 8; nb++)
#pragma unroll
                for (int e = 0; e < 4; e++) s[mt][nb][e] = 0.0f;

#pragma unroll
        for (int kb = 0; kb < 4; kb++) {
#pragma unroll
            for (int nb = 0; nb < 8; nb++) {
                int key = nb * 8 + g;
                int fk = FSW(key);
                uint32_t b0 = Kh[key * 32 + ((kb * 8 + t)     ^ fk)];
                uint32_t b1 = Kh[key * 32 + ((kb * 8 + t + 4) ^ fk)];
                mma_f16(s[0][nb], qa[0][kb], b0, b1);
                mma_f16(s[1][nb], qa[1][kb], b0, b1);
            }
        }

        // ---- Online softmax; pack P into fp16 A-frags (registers only) ----
        uint32_t pa[2][4][4];
#pragma unroll
        for (int mt = 0; mt < 2; mt++) {
#pragma unroll
            for (int hh = 0; hh < 2; hh++) {
                const int e0 = hh * 2;
                float mx = -1e30f;
#pragma unroll
                for (int nb = 0; nb < 8; nb++)
                    mx = fmaxf(mx, fmaxf(s[mt][nb][e0], s[mt][nb][e0 + 1]));
                mx = fmaxf(mx, __shfl_xor_sync(0xffffffffu, mx, 1));
                mx = fmaxf(mx, __shfl_xor_sync(0xffffffffu, mx, 2));
                float mnew = fmaxf(m_i[mt][hh], mx);
                float corr = __expf(m_i[mt][hh] - mnew);
                float rs = 0.0f;
#pragma unroll
                for (int nb = 0; nb < 8; nb++) {
                    float p0 = __expf(s[mt][nb][e0]     - mnew);
                    float p1 = __expf(s[mt][nb][e0 + 1] - mnew);
                    rs += p0 + p1;
                    s[mt][nb][e0]     = p0;
                    s[mt][nb][e0 + 1] = p1;
                }
                rs += __shfl_xor_sync(0xffffffffu, rs, 1);
                rs += __shfl_xor_sync(0xffffffffu, rs, 2);
                l_i[mt][hh] = l_i[mt][hh] * corr + rs;
                m_i[mt][hh] = mnew;
#pragma unroll
                for (int nb = 0; nb < 8; nb++) {
                    o[mt][nb][e0]     *= corr;
                    o[mt][nb][e0 + 1] *= corr;
                }
            }
#pragma unroll
            for (int kb = 0; kb < 4; kb++) {
                pa[mt][kb][0] = packh2(s[mt][2 * kb][0],     s[mt][2 * kb][1]);
                pa[mt][kb][1] = packh2(s[mt][2 * kb][2],     s[mt][2 * kb][3]);
                pa[mt][kb][2] = packh2(s[mt][2 * kb + 1][0], s[mt][2 * kb + 1][1]);
                pa[mt][kb][3] = packh2(s[mt][2 * kb + 1][2], s[mt][2 * kb + 1][3]);
            }
        }

        // ---- ctx += P @ V : 32x64 per warp ----
#pragma unroll
        for (int kb = 0; kb < 4; kb++) {
#pragma unroll
            for (int nb = 0; nb < 8; nb++) {
                int dim = nb * 8 + g;
                int fd = FSW(dim);
                uint32_t b0 = Vh[dim * 32 + ((kb * 8 + t)     ^ fd)];
                uint32_t b1 = Vh[dim * 32 + ((kb * 8 + t + 4) ^ fd)];
                mma_f16(o[0][nb], pa[0][kb], b0, b1);
                mma_f16(o[1][nb], pa[1][kb], b0, b1);
            }
        }
    }

    // ---- Normalize and write out[b, s, h*64 + d] ----
#pragma unroll
    for (int mt = 0; mt < 2; mt++)
#pragma unroll
        for (int hh = 0; hh < 2; hh++) {
            float inv_l = 1.0f / l_i[mt][hh];
            int row = q0 + warp * 32 + mt * 16 + g + 8 * hh;
#pragma unroll
            for (int nb = 0; nb < 8; nb++) {
                size_t base = (size_t)(b * SEQ + row) * HID + h * HD + nb * 8 + 2 * t;
                *(float2*)&out[base] = make_float2(o[mt][nb][2 * hh]     * inv_l,
                                                   o[mt][nb][2 * hh + 1] * inv_l);
            }
        }
}

// ---------------------------------------------------------------------------
extern "C" void kernel_launch(void* const* d_in, const int* in_sizes, int n_in,
                              void* d_out, int out_size) {
    const float* X  = (const float*)d_in[0];
    const float* Wq = (const float*)d_in[1];
    const float* Wk = (const float*)d_in[2];
    const float* Wv = (const float*)d_in[3];
    float* out = (float*)d_out;

    qkv_gemm<<<dim3(HID / 128, MROWS / 128, 3), 256>>>(X, Wq, Wk, Wv);
    rope_table<<<(SEQ * 32 + 255) / 256, 256>>>();
    attn_kernel<<<dim3(SEQ / 128, NH * BATCH), 128>>>(out);
}

// round 13
// speedup vs baseline: 1.0824x; 1.0805x over previous
#include <cuda_runtime.h>
#include <cuda_fp16.h>
#include <math.h>
#include <stdint.h>

#define BATCH 2
#define SEQ   2048
#define NH    16
#define HD    64
#define HID   1024            // NH*HD
#define MROWS (BATCH*SEQ)     // 4096

// Scratch (no allocations allowed). q/k/v stored as half2 words in
// [B][H][S][64] layout: word index = ((b*16+h)*2048 + s)*32 + (d>>1).
__device__ uint32_t g_qh[MROWS * HID / 2];
__device__ uint32_t g_kh[MROWS * HID / 2];
__device__ uint32_t g_vh[MROWS * HID / 2];
__device__ float g_cos[SEQ * 32];
__device__ float g_sin[SEQ * 32];

#define QSCALE (0.125f * 1.44269504088896f)   // 1/sqrt(64) * log2(e), folded into Q

__device__ __forceinline__ void mma_f16(float c[4], const uint32_t a[4],
                                        uint32_t b0, uint32_t b1) {
    asm volatile(
        "mma.sync.aligned.m16n8k16.row.col.f32.f16.f16.f32 "
        "{%0,%1,%2,%3},{%4,%5,%6,%7},{%8,%9},{%0,%1,%2,%3};"
        : "+f"(c[0]), "+f"(c[1]), "+f"(c[2]), "+f"(c[3])
        : "r"(a[0]), "r"(a[1]), "r"(a[2]), "r"(a[3]), "r"(b0), "r"(b1));
}

__device__ __forceinline__ uint32_t packh2(float lo, float hi) {
    __half2 h = __floats2half2_rn(lo, hi);
    return *(uint32_t*)&h;
}
__device__ __forceinline__ uint32_t h2u(__half2 h) { return *(uint32_t*)&h; }
__device__ __forceinline__ __half2 u2h(uint32_t u) { return *(__half2*)&u; }

// Bank-spread swizzle key for [row][pair] half2 layouts (32 words/row).
__device__ __forceinline__ int FSW(int d) { return ((d & 7) << 2) | ((d >> 3) & 3); }

// ---------------------------------------------------------------------------
// RoPE tables — must run BEFORE qkv_gemm (epilogue applies RoPE).
// ---------------------------------------------------------------------------
__global__ void rope_table() {
    int idx = blockIdx.x * blockDim.x + threadIdx.x;
    if (idx >= SEQ * 32) return;
    int s = idx >> 5;
    int j = idx & 31;
    double inv = pow(10000.0, -(double)j / 32.0);
    double a = (double)s * inv;
    g_cos[idx] = (float)cos(a);
    g_sin[idx] = (float)sin(a);
}

// ---------------------------------------------------------------------------
// QKV projection, fp16 m16n8k16: Y = X @ W^T. Epilogue: RoPE (q,k) + fp16
// convert + per-head [B,H,S,64] half layout. Q pre-scaled by QSCALE.
// Block tile 128x128, K-step 32. 8 warps in 4x2 (warp tile 32x64).
// ---------------------------------------------------------------------------
#define QPAD 20
__global__ __launch_bounds__(256)
void qkv_gemm(const float* __restrict__ X,
              const float* __restrict__ Wq,
              const float* __restrict__ Wk,
              const float* __restrict__ Wv) {
    __shared__ uint32_t As2[128 * QPAD];
    __shared__ uint32_t Bs2[128 * QPAD];

    const int z = blockIdx.z;
    const float* W = (z == 0) ? Wq : (z == 1) ? Wk : Wv;
    uint32_t* Yh   = (z == 0) ? g_qh : (z == 1) ? g_kh : g_vh;

    const int m0 = blockIdx.y * 128;
    const int n0 = blockIdx.x * 128;
    const int tid  = threadIdx.x;
    const int warp = tid >> 5;
    const int lane = tid & 31;
    const int g = lane >> 2;
    const int t = lane & 3;
    const int wm0 = (warp >> 1) * 32;   // 0,32,64,96
    const int wn0 = (warp & 1) * 64;    // 0,64

    float acc[2][8][4];
#pragma unroll
    for (int mt = 0; mt < 2; mt++)
#pragma unroll
        for (int nt = 0; nt < 8; nt++)
#pragma unroll
            for (int e = 0; e < 4; e++) acc[mt][nt][e] = 0.0f;

    for (int k0 = 0; k0 < HID; k0 += 32) {
#pragma unroll
        for (int u = 0; u < 4; u++) {
            int idx = tid + u * 256;
            int row = idx >> 3;          // 0..127
            int c4  = (idx & 7) * 4;     // 0..28
            int w0  = row * QPAD + (c4 >> 1);
            float4 xa = *(const float4*)&X[(size_t)(m0 + row) * HID + k0 + c4];
            As2[w0]     = packh2(xa.x, xa.y);
            As2[w0 + 1] = packh2(xa.z, xa.w);
            float4 wb = *(const float4*)&W[(size_t)(n0 + row) * HID + k0 + c4];
            Bs2[w0]     = packh2(wb.x, wb.y);
            Bs2[w0 + 1] = packh2(wb.z, wb.w);
        }
        __syncthreads();

#pragma unroll
        for (int kb = 0; kb < 2; kb++) {
            uint32_t a[2][4];
#pragma unroll
            for (int mt = 0; mt < 2; mt++) {
                int ra = (wm0 + mt * 16 + g) * QPAD;
                int rb = (wm0 + mt * 16 + 8 + g) * QPAD;
                a[mt][0] = As2[ra + kb * 8 + t];
                a[mt][1] = As2[rb + kb * 8 + t];
                a[mt][2] = As2[ra + kb * 8 + 4 + t];
                a[mt][3] = As2[rb + kb * 8 + 4 + t];
            }
#pragma unroll
            for (int nt = 0; nt < 8; nt++) {
                int rc = (wn0 + nt * 8 + g) * QPAD;
                uint32_t b0 = Bs2[rc + kb * 8 + t];
                uint32_t b1 = Bs2[rc + kb * 8 + 4 + t];
                mma_f16(acc[0][nt], a[0], b0, b1);
                mma_f16(acc[1][nt], a[1], b0, b1);
            }
        }
        __syncthreads();
    }

    // ---- Epilogue: RoPE (z<2) + fp16 + per-head layout ----
    const int head = (n0 + wn0) >> 6;   // this warp covers exactly one head
    const float sc = (z == 0) ? QSCALE : 1.0f;
#pragma unroll
    for (int mt = 0; mt < 2; mt++) {
        int r0 = m0 + wm0 + mt * 16 + g;        // rows r0 and r0+8
        int bq = r0 >> 11;
        int s0 = r0 & 2047;
        size_t base0 = ((size_t)(bq * 16 + head) * 2048 + s0) * 32;
        size_t base1 = base0 + 8 * 32;
        if (z < 2) {
#pragma unroll
            for (int nt = 0; nt < 4; nt++) {
                int j = nt * 8 + 2 * t;          // dim 0..30 (pairs with +32)
                float2 c0  = *(const float2*)&g_cos[s0 * 32 + j];
                float2 sn0 = *(const float2*)&g_sin[s0 * 32 + j];
                float2 c1  = *(const float2*)&g_cos[(s0 + 8) * 32 + j];
                float2 sn1 = *(const float2*)&g_sin[(s0 + 8) * 32 + j];
                float lo0 = acc[mt][nt][0],     lo1 = acc[mt][nt][1];
                float hi0 = acc[mt][nt + 4][0], hi1 = acc[mt][nt + 4][1];
                float lo2 = acc[mt][nt][2],     lo3 = acc[mt][nt][3];
                float hi2 = acc[mt][nt + 4][2], hi3 = acc[mt][nt + 4][3];
                int wl = nt * 4 + t;
                Yh[base0 + wl]      = packh2((lo0 * c0.x - hi0 * sn0.x) * sc,
                                             (lo1 * c0.y - hi1 * sn0.y) * sc);
                Yh[base0 + wl + 16] = packh2((hi0 * c0.x + lo0 * sn0.x) * sc,
                                             (hi1 * c0.y + lo1 * sn0.y) * sc);
                Yh[base1 + wl]      = packh2((lo2 * c1.x - hi2 * sn1.x) * sc,
                                             (lo3 * c1.y - hi3 * sn1.y) * sc);
                Yh[base1 + wl + 16] = packh2((hi2 * c1.x + lo2 * sn1.x) * sc,
                                             (hi3 * c1.y + lo3 * sn1.y) * sc);
            }
        } else {
#pragma unroll
            for (int nt = 0; nt < 8; nt++) {
                int wl = nt * 4 + t;
                Yh[base0 + wl] = packh2(acc[mt][nt][0], acc[mt][nt][1]);
                Yh[base1 + wl] = packh2(acc[mt][nt][2], acc[mt][nt][3]);
            }
        }
    }
}

// ---------------------------------------------------------------------------
// Flash attention, fp16 m16n8k16. Staging is now pure data movement from
// pre-RoPE'd half buffers; softmax in exp2 domain (log2e folded into Q).
// ---------------------------------------------------------------------------
__global__ __launch_bounds__(128)
void attn_kernel(float* __restrict__ out) {
    __shared__ uint32_t sh[4096];     // 16 KB
    uint32_t* Kh = sh;                // 2048 words
    uint32_t* Vh = sh + 2048;         // 2048 words

    const int tid  = threadIdx.x;
    const int warp = tid >> 5;
    const int lane = tid & 31;
    const int g = lane >> 2;
    const int t = lane & 3;
    const int h = blockIdx.y & (NH - 1);
    const int b = blockIdx.y >> 4;
    const int q0 = blockIdx.x * 128;

    const uint32_t* qh = g_qh + (size_t)(b * 16 + h) * 2048 * 32;
    const uint32_t* kh = g_kh + (size_t)(b * 16 + h) * 2048 * 32;
    const uint32_t* vh = g_vh + (size_t)(b * 16 + h) * 2048 * 32;

    // ---- Stage this warp's 32 Q rows (pure copy), grab frags ----
    uint32_t* Qs = sh + warp * 1024;  // 32 rows x 32 words
#pragma unroll
    for (int it = 0; it < 8; it++) {
        int idx = lane + it * 32;     // 0..255
        int r  = idx >> 3;
        int wq = (idx & 7) * 4;
        uint4 w = *(const uint4*)&qh[(size_t)(q0 + warp * 32 + r) * 32 + wq];
        int fr = FSW(r);
        Qs[r * 32 + ((wq + 0) ^ fr)] = w.x;
        Qs[r * 32 + ((wq + 1) ^ fr)] = w.y;
        Qs[r * 32 + ((wq + 2) ^ fr)] = w.z;
        Qs[r * 32 + ((wq + 3) ^ fr)] = w.w;
    }
    __syncwarp();
    uint32_t qa[2][4][4];
#pragma unroll
    for (int mt = 0; mt < 2; mt++) {
        int ra = mt * 16 + g, rb = mt * 16 + 8 + g;
        int fa = FSW(ra), fb = FSW(rb);
#pragma unroll
        for (int kb = 0; kb < 4; kb++) {
            qa[mt][kb][0] = Qs[ra * 32 + ((kb * 8 + t)     ^ fa)];
            qa[mt][kb][1] = Qs[rb * 32 + ((kb * 8 + t)     ^ fb)];
            qa[mt][kb][2] = Qs[ra * 32 + ((kb * 8 + t + 4) ^ fa)];
            qa[mt][kb][3] = Qs[rb * 32 + ((kb * 8 + t + 4) ^ fb)];
        }
    }

    float m_i[2][2], l_i[2][2];
    float o[2][8][4];
#pragma unroll
    for (int mt = 0; mt < 2; mt++) {
        m_i[mt][0] = m_i[mt][1] = -1e30f;
        l_i[mt][0] = l_i[mt][1] = 0.0f;
#pragma unroll
        for (int nb = 0; nb < 8; nb++)
#pragma unroll
            for (int e = 0; e < 4; e++) o[mt][nb][e] = 0.0f;
    }

    for (int k0 = 0; k0 < SEQ; k0 += 64) {
        __syncthreads();

        // ---- Stage K (pure copy, swizzled) ----
#pragma unroll
        for (int u = 0; u < 4; u++) {
            int idx = tid + u * 128;      // 0..511
            int r  = idx >> 3;            // key row 0..63
            int wq = (idx & 7) * 4;
            uint4 w = *(const uint4*)&kh[(size_t)(k0 + r) * 32 + wq];
            int fr = FSW(r);
            Kh[r * 32 + ((wq + 0) ^ fr)] = w.x;
            Kh[r * 32 + ((wq + 1) ^ fr)] = w.y;
            Kh[r * 32 + ((wq + 2) ^ fr)] = w.z;
            Kh[r * 32 + ((wq + 3) ^ fr)] = w.w;
        }
        // ---- Stage V transposed: Vh[dim][keypair] ----
#pragma unroll
        for (int u = 0; u < 4; u++) {
            int idx = tid + u * 128;      // 0..511
            int kp = idx >> 4;            // key pair 0..31
            int dq = idx & 15;            // dim quad: dims dq*4..+3
            uint2 a = *(const uint2*)&vh[(size_t)(k0 + 2 * kp) * 32 + dq * 2];
            uint2 c = *(const uint2*)&vh[(size_t)(k0 + 2 * kp + 1) * 32 + dq * 2];
            __half2 a0 = u2h(a.x), a1 = u2h(a.y);
            __half2 c0 = u2h(c.x), c1 = u2h(c.y);
            int d0 = dq * 4;
            Vh[(d0 + 0) * 32 + (kp ^ FSW(d0 + 0))] = h2u(__lows2half2(a0, c0));
            Vh[(d0 + 1) * 32 + (kp ^ FSW(d0 + 1))] = h2u(__highs2half2(a0, c0));
            Vh[(d0 + 2) * 32 + (kp ^ FSW(d0 + 2))] = h2u(__lows2half2(a1, c1));
            Vh[(d0 + 3) * 32 + (kp ^ FSW(d0 + 3))] = h2u(__highs2half2(a1, c1));
        }
        __syncthreads();

        // ---- S = Q @ K^T : 32x64 per warp (scores already in log2 domain) ----
        float s[2][8][4];
#pragma unroll
        for (int mt = 0; mt < 2; mt++)
#pragma unroll
            for (int nb = 0; nb < 8; nb++)
#pragma unroll
                for (int e = 0; e < 4; e++) s[mt][nb][e] = 0.0f;

#pragma unroll
        for (int kb = 0; kb < 4; kb++) {
#pragma unroll
            for (int nb = 0; nb < 8; nb++) {
                int key = nb * 8 + g;
                int fk = FSW(key);
                uint32_t b0 = Kh[key * 32 + ((kb * 8 + t)     ^ fk)];
                uint32_t b1 = Kh[key * 32 + ((kb * 8 + t + 4) ^ fk)];
                mma_f16(s[0][nb], qa[0][kb], b0, b1);
                mma_f16(s[1][nb], qa[1][kb], b0, b1);
            }
        }

        // ---- Online softmax (exp2 domain); pack P into fp16 A-frags ----
        uint32_t pa[2][4][4];
#pragma unroll
        for (int mt = 0; mt < 2; mt++) {
#pragma unroll
            for (int hh = 0; hh < 2; hh++) {
                const int e0 = hh * 2;
                float mx = -1e30f;
#pragma unroll
                for (int nb = 0; nb < 8; nb++)
                    mx = fmaxf(mx, fmaxf(s[mt][nb][e0], s[mt][nb][e0 + 1]));
                mx = fmaxf(mx, __shfl_xor_sync(0xffffffffu, mx, 1));
                mx = fmaxf(mx, __shfl_xor_sync(0xffffffffu, mx, 2));
                float mnew = fmaxf(m_i[mt][hh], mx);
                float corr = exp2f(m_i[mt][hh] - mnew);
                float rs = 0.0f;
#pragma unroll
                for (int nb = 0; nb < 8; nb++) {
                    float p0 = exp2f(s[mt][nb][e0]     - mnew);
                    float p1 = exp2f(s[mt][nb][e0 + 1] - mnew);
                    rs += p0 + p1;
                    s[mt][nb][e0]     = p0;
                    s[mt][nb][e0 + 1] = p1;
                }
                rs += __shfl_xor_sync(0xffffffffu, rs, 1);
                rs += __shfl_xor_sync(0xffffffffu, rs, 2);
                l_i[mt][hh] = l_i[mt][hh] * corr + rs;
                m_i[mt][hh] = mnew;
#pragma unroll
                for (int nb = 0; nb < 8; nb++) {
                    o[mt][nb][e0]     *= corr;
                    o[mt][nb][e0 + 1] *= corr;
                }
            }
#pragma unroll
            for (int kb = 0; kb < 4; kb++) {
                pa[mt][kb][0] = packh2(s[mt][2 * kb][0],     s[mt][2 * kb][1]);
                pa[mt][kb][1] = packh2(s[mt][2 * kb][2],     s[mt][2 * kb][3]);
                pa[mt][kb][2] = packh2(s[mt][2 * kb + 1][0], s[mt][2 * kb + 1][1]);
                pa[mt][kb][3] = packh2(s[mt][2 * kb + 1][2], s[mt][2 * kb + 1][3]);
            }
        }

        // ---- ctx += P @ V : 32x64 per warp ----
#pragma unroll
        for (int kb = 0; kb < 4; kb++) {
#pragma unroll
            for (int nb = 0; nb < 8; nb++) {
                int dim = nb * 8 + g;
                int fd = FSW(dim);
                uint32_t b0 = Vh[dim * 32 + ((kb * 8 + t)     ^ fd)];
                uint32_t b1 = Vh[dim * 32 + ((kb * 8 + t + 4) ^ fd)];
                mma_f16(o[0][nb], pa[0][kb], b0, b1);
                mma_f16(o[1][nb], pa[1][kb], b0, b1);
            }
        }
    }

    // ---- Normalize and write out[b, s, h*64 + d] ----
#pragma unroll
    for (int mt = 0; mt < 2; mt++)
#pragma unroll
        for (int hh = 0; hh < 2; hh++) {
            float inv_l = 1.0f / l_i[mt][hh];
            int row = q0 + warp * 32 + mt * 16 + g + 8 * hh;
#pragma unroll
            for (int nb = 0; nb < 8; nb++) {
                size_t base = (size_t)(b * SEQ + row) * HID + h * HD + nb * 8 + 2 * t;
                *(float2*)&out[base] = make_float2(o[mt][nb][2 * hh]     * inv_l,
                                                   o[mt][nb][2 * hh + 1] * inv_l);
            }
        }
}

// ---------------------------------------------------------------------------
extern "C" void kernel_launch(void* const* d_in, const int* in_sizes, int n_in,
                              void* d_out, int out_size) {
    const float* X  = (const float*)d_in[0];
    const float* Wq = (const float*)d_in[1];
    const float* Wk = (const float*)d_in[2];
    const float* Wv = (const float*)d_in[3];
    float* out = (float*)d_out;

    rope_table<<<(SEQ * 32 + 255) / 256, 256>>>();
    qkv_gemm<<<dim3(HID / 128, MROWS / 128, 3), 256>>>(X, Wq, Wk, Wv);
    attn_kernel<<<dim3(SEQ / 128, NH * BATCH), 128>>>(out);
}

// round 14
// speedup vs baseline: 1.0918x; 1.0087x over previous
#include <cuda_runtime.h>
#include <cuda_fp16.h>
#include <math.h>
#include <stdint.h>

#define BATCH 2
#define SEQ   2048
#define NH    16
#define HD    64
#define HID   1024            // NH*HD
#define MROWS (BATCH*SEQ)     // 4096

// Scratch (no allocations allowed). q/k/v stored as half2 words in
// [B][H][S][64] layout: word index = ((b*16+h)*2048 + s)*32 + (d>>1).
__device__ uint32_t g_qh[MROWS * HID / 2];
__device__ uint32_t g_kh[MROWS * HID / 2];
__device__ uint32_t g_vh[MROWS * HID / 2];
// fp16 copies of the inputs (half2 words, row-major pairs along K)
__device__ uint32_t g_xh[MROWS * HID / 2];          // X  [4096][512]
__device__ uint32_t g_wh[3 * HID * HID / 2];        // Wq|Wk|Wv [1024][512] each
__device__ float g_cos[SEQ * 32];
__device__ float g_sin[SEQ * 32];

#define QSCALE (0.125f * 1.44269504088896f)   // 1/sqrt(64) * log2(e), folded into Q

__device__ __forceinline__ void mma_f16(float c[4], const uint32_t a[4],
                                        uint32_t b0, uint32_t b1) {
    asm volatile(
        "mma.sync.aligned.m16n8k16.row.col.f32.f16.f16.f32 "
        "{%0,%1,%2,%3},{%4,%5,%6,%7},{%8,%9},{%0,%1,%2,%3};"
        : "+f"(c[0]), "+f"(c[1]), "+f"(c[2]), "+f"(c[3])
        : "r"(a[0]), "r"(a[1]), "r"(a[2]), "r"(a[3]), "r"(b0), "r"(b1));
}

__device__ __forceinline__ uint32_t packh2(float lo, float hi) {
    __half2 h = __floats2half2_rn(lo, hi);
    return *(uint32_t*)&h;
}
__device__ __forceinline__ uint32_t h2u(__half2 h) { return *(uint32_t*)&h; }
__device__ __forceinline__ __half2 u2h(uint32_t u) { return *(__half2*)&u; }

// Bank-spread swizzle key for [row][pair] half2 layouts (32 words/row).
__device__ __forceinline__ int FSW(int d) { return ((d & 7) << 2) | ((d >> 3) & 3); }

// ---------------------------------------------------------------------------
// fp32 -> fp16 bulk convert (X and W, once per launch)
// ---------------------------------------------------------------------------
__global__ void to_half(const float* __restrict__ src, uint32_t* __restrict__ dst,
                        int n4) {
    int i = blockIdx.x * blockDim.x + threadIdx.x;
    if (i >= n4) return;
    float4 v = ((const float4*)src)[i];
    ((uint2*)dst)[i] = make_uint2(packh2(v.x, v.y), packh2(v.z, v.w));
}

// ---------------------------------------------------------------------------
// RoPE tables — fp32 math, matching the reference's own fp32 computation.
// ---------------------------------------------------------------------------
__global__ void rope_table() {
    int idx = blockIdx.x * blockDim.x + threadIdx.x;
    if (idx >= SEQ * 32) return;
    int s = idx >> 5;
    int j = idx & 31;
    // inv_freq = 10000^(-j/32) = exp(-j/32 * ln(10000))
    float inv = __expf((float)j * (-9.210340371976184f / 32.0f));
    float a = (float)s * inv;
    float sn, cs;
    sincosf(a, &sn, &cs);
    g_cos[idx] = cs;
    g_sin[idx] = sn;
}

// ---------------------------------------------------------------------------
// QKV projection, fp16 m16n8k16: Y = X @ W^T, inputs pre-converted to half.
// Epilogue: RoPE (q,k) + per-head [B,H,S,64] half layout; Q scaled by QSCALE.
// Block tile 128x128, K-step 32. 8 warps in 4x2 (warp tile 32x64).
// ---------------------------------------------------------------------------
#define QPAD 20
__global__ __launch_bounds__(256)
void qkv_gemm() {
    __shared__ uint32_t As2[128 * QPAD];
    __shared__ uint32_t Bs2[128 * QPAD];

    const int z = blockIdx.z;
    const uint32_t* Wh = g_wh + (size_t)z * (HID * HID / 2);
    uint32_t* Yh       = (z == 0) ? g_qh : (z == 1) ? g_kh : g_vh;

    const int m0 = blockIdx.y * 128;
    const int n0 = blockIdx.x * 128;
    const int tid  = threadIdx.x;
    const int warp = tid >> 5;
    const int lane = tid & 31;
    const int g = lane >> 2;
    const int t = lane & 3;
    const int wm0 = (warp >> 1) * 32;   // 0,32,64,96
    const int wn0 = (warp & 1) * 64;    // 0,64

    float acc[2][8][4];
#pragma unroll
    for (int mt = 0; mt < 2; mt++)
#pragma unroll
        for (int nt = 0; nt < 8; nt++)
#pragma unroll
            for (int e = 0; e < 4; e++) acc[mt][nt][e] = 0.0f;

    for (int k0 = 0; k0 < HID; k0 += 32) {
        // Stage A and B tiles straight from half buffers (pure copy)
#pragma unroll
        for (int u = 0; u < 4; u++) {
            int idx = tid + u * 256;
            int row = idx >> 3;          // 0..127
            int c4  = (idx & 7) * 4;     // 0..28
            int w0  = row * QPAD + (c4 >> 1);
            uint2 xa = *(const uint2*)&g_xh[(size_t)(m0 + row) * 512 + ((k0 + c4) >> 1)];
            As2[w0]     = xa.x;
            As2[w0 + 1] = xa.y;
            uint2 wb = *(const uint2*)&Wh[(size_t)(n0 + row) * 512 + ((k0 + c4) >> 1)];
            Bs2[w0]     = wb.x;
            Bs2[w0 + 1] = wb.y;
        }
        __syncthreads();

#pragma unroll
        for (int kb = 0; kb < 2; kb++) {
            uint32_t a[2][4];
#pragma unroll
            for (int mt = 0; mt < 2; mt++) {
                int ra = (wm0 + mt * 16 + g) * QPAD;
                int rb = (wm0 + mt * 16 + 8 + g) * QPAD;
                a[mt][0] = As2[ra + kb * 8 + t];
                a[mt][1] = As2[rb + kb * 8 + t];
                a[mt][2] = As2[ra + kb * 8 + 4 + t];
                a[mt][3] = As2[rb + kb * 8 + 4 + t];
            }
#pragma unroll
            for (int nt = 0; nt < 8; nt++) {
                int rc = (wn0 + nt * 8 + g) * QPAD;
                uint32_t b0 = Bs2[rc + kb * 8 + t];
                uint32_t b1 = Bs2[rc + kb * 8 + 4 + t];
                mma_f16(acc[0][nt], a[0], b0, b1);
                mma_f16(acc[1][nt], a[1], b0, b1);
            }
        }
        __syncthreads();
    }

    // ---- Epilogue: RoPE (z<2) + fp16 + per-head layout ----
    const int head = (n0 + wn0) >> 6;   // this warp covers exactly one head
    const float sc = (z == 0) ? QSCALE : 1.0f;
#pragma unroll
    for (int mt = 0; mt < 2; mt++) {
        int r0 = m0 + wm0 + mt * 16 + g;        // rows r0 and r0+8
        int bq = r0 >> 11;
        int s0 = r0 & 2047;
        size_t base0 = ((size_t)(bq * 16 + head) * 2048 + s0) * 32;
        size_t base1 = base0 + 8 * 32;
        if (z < 2) {
#pragma unroll
            for (int nt = 0; nt < 4; nt++) {
                int j = nt * 8 + 2 * t;          // dim 0..30 (pairs with +32)
                float2 c0  = *(const float2*)&g_cos[s0 * 32 + j];
                float2 sn0 = *(const float2*)&g_sin[s0 * 32 + j];
                float2 c1  = *(const float2*)&g_cos[(s0 + 8) * 32 + j];
                float2 sn1 = *(const float2*)&g_sin[(s0 + 8) * 32 + j];
                float lo0 = acc[mt][nt][0],     lo1 = acc[mt][nt][1];
                float hi0 = acc[mt][nt + 4][0], hi1 = acc[mt][nt + 4][1];
                float lo2 = acc[mt][nt][2],     lo3 = acc[mt][nt][3];
                float hi2 = acc[mt][nt + 4][2], hi3 = acc[mt][nt + 4][3];
                int wl = nt * 4 + t;
                Yh[base0 + wl]      = packh2((lo0 * c0.x - hi0 * sn0.x) * sc,
                                             (lo1 * c0.y - hi1 * sn0.y) * sc);
                Yh[base0 + wl + 16] = packh2((hi0 * c0.x + lo0 * sn0.x) * sc,
                                             (hi1 * c0.y + lo1 * sn0.y) * sc);
                Yh[base1 + wl]      = packh2((lo2 * c1.x - hi2 * sn1.x) * sc,
                                             (lo3 * c1.y - hi3 * sn1.y) * sc);
                Yh[base1 + wl + 16] = packh2((hi2 * c1.x + lo2 * sn1.x) * sc,
                                             (hi3 * c1.y + lo3 * sn1.y) * sc);
            }
        } else {
#pragma unroll
            for (int nt = 0; nt < 8; nt++) {
                int wl = nt * 4 + t;
                Yh[base0 + wl] = packh2(acc[mt][nt][0], acc[mt][nt][1]);
                Yh[base1 + wl] = packh2(acc[mt][nt][2], acc[mt][nt][3]);
            }
        }
    }
}

// ---------------------------------------------------------------------------
// Flash attention, fp16 m16n8k16 (unchanged — known good).
// ---------------------------------------------------------------------------
__global__ __launch_bounds__(128)
void attn_kernel(float* __restrict__ out) {
    __shared__ uint32_t sh[4096];     // 16 KB
    uint32_t* Kh = sh;                // 2048 words
    uint32_t* Vh = sh + 2048;         // 2048 words

    const int tid  = threadIdx.x;
    const int warp = tid >> 5;
    const int lane = tid & 31;
    const int g = lane >> 2;
    const int t = lane & 3;
    const int h = blockIdx.y & (NH - 1);
    const int b = blockIdx.y >> 4;
    const int q0 = blockIdx.x * 128;

    const uint32_t* qh = g_qh + (size_t)(b * 16 + h) * 2048 * 32;
    const uint32_t* kh = g_kh + (size_t)(b * 16 + h) * 2048 * 32;
    const uint32_t* vh = g_vh + (size_t)(b * 16 + h) * 2048 * 32;

    // ---- Stage this warp's 32 Q rows (pure copy), grab frags ----
    uint32_t* Qs = sh + warp * 1024;  // 32 rows x 32 words
#pragma unroll
    for (int it = 0; it < 8; it++) {
        int idx = lane + it * 32;     // 0..255
        int r  = idx >> 3;
        int wq = (idx & 7) * 4;
        uint4 w = *(const uint4*)&qh[(size_t)(q0 + warp * 32 + r) * 32 + wq];
        int fr = FSW(r);
        Qs[r * 32 + ((wq + 0) ^ fr)] = w.x;
        Qs[r * 32 + ((wq + 1) ^ fr)] = w.y;
        Qs[r * 32 + ((wq + 2) ^ fr)] = w.z;
        Qs[r * 32 + ((wq + 3) ^ fr)] = w.w;
    }
    __syncwarp();
    uint32_t qa[2][4][4];
#pragma unroll
    for (int mt = 0; mt < 2; mt++) {
        int ra = mt * 16 + g, rb = mt * 16 + 8 + g;
        int fa = FSW(ra), fb = FSW(rb);
#pragma unroll
        for (int kb = 0; kb < 4; kb++) {
            qa[mt][kb][0] = Qs[ra * 32 + ((kb * 8 + t)     ^ fa)];
            qa[mt][kb][1] = Qs[rb * 32 + ((kb * 8 + t)     ^ fb)];
            qa[mt][kb][2] = Qs[ra * 32 + ((kb * 8 + t + 4) ^ fa)];
            qa[mt][kb][3] = Qs[rb * 32 + ((kb * 8 + t + 4) ^ fb)];
        }
    }

    float m_i[2][2], l_i[2][2];
    float o[2][8][4];
#pragma unroll
    for (int mt = 0; mt < 2; mt++) {
        m_i[mt][0] = m_i[mt][1] = -1e30f;
        l_i[mt][0] = l_i[mt][1] = 0.0f;
#pragma unroll
        for (int nb = 0; nb < 8; nb++)
#pragma unroll
            for (int e = 0; e < 4; e++) o[mt][nb][e] = 0.0f;
    }

    for (int k0 = 0; k0 < SEQ; k0 += 64) {
        __syncthreads();

        // ---- Stage K (pure copy, swizzled) ----
#pragma unroll
        for (int u = 0; u < 4; u++) {
            int idx = tid + u * 128;      // 0..511
            int r  = idx >> 3;            // key row 0..63
            int wq = (idx & 7) * 4;
            uint4 w = *(const uint4*)&kh[(size_t)(k0 + r) * 32 + wq];
            int fr = FSW(r);
            Kh[r * 32 + ((wq + 0) ^ fr)] = w.x;
            Kh[r * 32 + ((wq + 1) ^ fr)] = w.y;
            Kh[r * 32 + ((wq + 2) ^ fr)] = w.z;
            Kh[r * 32 + ((wq + 3) ^ fr)] = w.w;
        }
        // ---- Stage V transposed: Vh[dim][keypair] ----
#pragma unroll
        for (int u = 0; u < 4; u++) {
            int idx = tid + u * 128;      // 0..511
            int kp = idx >> 4;            // key pair 0..31
            int dq = idx & 15;            // dim quad: dims dq*4..+3
            uint2 a = *(const uint2*)&vh[(size_t)(k0 + 2 * kp) * 32 + dq * 2];
            uint2 c = *(const uint2*)&vh[(size_t)(k0 + 2 * kp + 1) * 32 + dq * 2];
            __half2 a0 = u2h(a.x), a1 = u2h(a.y);
            __half2 c0 = u2h(c.x), c1 = u2h(c.y);
            int d0 = dq * 4;
            Vh[(d0 + 0) * 32 + (kp ^ FSW(d0 + 0))] = h2u(__lows2half2(a0, c0));
            Vh[(d0 + 1) * 32 + (kp ^ FSW(d0 + 1))] = h2u(__highs2half2(a0, c0));
            Vh[(d0 + 2) * 32 + (kp ^ FSW(d0 + 2))] = h2u(__lows2half2(a1, c1));
            Vh[(d0 + 3) * 32 + (kp ^ FSW(d0 + 3))] = h2u(__highs2half2(a1, c1));
        }
        __syncthreads();

        // ---- S = Q @ K^T : 32x64 per warp (scores already in log2 domain) ----
        float s[2][8][4];
#pragma unroll
        for (int mt = 0; mt < 2; mt++)
#pragma unroll
            for (int nb = 0; nb < 8; nb++)
#pragma unroll
                for (int e = 0; e < 4; e++) s[mt][nb][e] = 0.0f;

#pragma unroll
        for (int kb = 0; kb < 4; kb++) {
#pragma unroll
            for (int nb = 0; nb < 8; nb++) {
                int key = nb * 8 + g;
                int fk = FSW(key);
                uint32_t b0 = Kh[key * 32 + ((kb * 8 + t)     ^ fk)];
                uint32_t b1 = Kh[key * 32 + ((kb * 8 + t + 4) ^ fk)];
                mma_f16(s[0][nb], qa[0][kb], b0, b1);
                mma_f16(s[1][nb], qa[1][kb], b0, b1);
            }
        }

        // ---- Online softmax (exp2 domain); pack P into fp16 A-frags ----
        uint32_t pa[2][4][4];
#pragma unroll
        for (int mt = 0; mt < 2; mt++) {
#pragma unroll
            for (int hh = 0; hh < 2; hh++) {
                const int e0 = hh * 2;
                float mx = -1e30f;
#pragma unroll
                for (int nb = 0; nb < 8; nb++)
                    mx = fmaxf(mx, fmaxf(s[mt][nb][e0], s[mt][nb][e0 + 1]));
                mx = fmaxf(mx, __shfl_xor_sync(0xffffffffu, mx, 1));
                mx = fmaxf(mx, __shfl_xor_sync(0xffffffffu, mx, 2));
                float mnew = fmaxf(m_i[mt][hh], mx);
                float corr = exp2f(m_i[mt][hh] - mnew);
                float rs = 0.0f;
#pragma unroll
                for (int nb = 0; nb < 8; nb++) {
                    float p0 = exp2f(s[mt][nb][e0]     - mnew);
                    float p1 = exp2f(s[mt][nb][e0 + 1] - mnew);
                    rs += p0 + p1;
                    s[mt][nb][e0]     = p0;
                    s[mt][nb][e0 + 1] = p1;
                }
                rs += __shfl_xor_sync(0xffffffffu, rs, 1);
                rs += __shfl_xor_sync(0xffffffffu, rs, 2);
                l_i[mt][hh] = l_i[mt][hh] * corr + rs;
                m_i[mt][hh] = mnew;
#pragma unroll
                for (int nb = 0; nb < 8; nb++) {
                    o[mt][nb][e0]     *= corr;
                    o[mt][nb][e0 + 1] *= corr;
                }
            }
#pragma unroll
            for (int kb = 0; kb < 4; kb++) {
                pa[mt][kb][0] = packh2(s[mt][2 * kb][0],     s[mt][2 * kb][1]);
                pa[mt][kb][1] = packh2(s[mt][2 * kb][2],     s[mt][2 * kb][3]);
                pa[mt][kb][2] = packh2(s[mt][2 * kb + 1][0], s[mt][2 * kb + 1][1]);
                pa[mt][kb][3] = packh2(s[mt][2 * kb + 1][2], s[mt][2 * kb + 1][3]);
            }
        }

        // ---- ctx += P @ V : 32x64 per warp ----
#pragma unroll
        for (int kb = 0; kb < 4; kb++) {
#pragma unroll
            for (int nb = 0; nb < 8; nb++) {
                int dim = nb * 8 + g;
                int fd = FSW(dim);
                uint32_t b0 = Vh[dim * 32 + ((kb * 8 + t)     ^ fd)];
                uint32_t b1 = Vh[dim * 32 + ((kb * 8 + t + 4) ^ fd)];
                mma_f16(o[0][nb], pa[0][kb], b0, b1);
                mma_f16(o[1][nb], pa[1][kb], b0, b1);
            }
        }
    }

    // ---- Normalize and write out[b, s, h*64 + d] ----
#pragma unroll
    for (int mt = 0; mt < 2; mt++)
#pragma unroll
        for (int hh = 0; hh < 2; hh++) {
            float inv_l = 1.0f / l_i[mt][hh];
            int row = q0 + warp * 32 + mt * 16 + g + 8 * hh;
#pragma unroll
            for (int nb = 0; nb < 8; nb++) {
                size_t base = (size_t)(b * SEQ + row) * HID + h * HD + nb * 8 + 2 * t;
                *(float2*)&out[base] = make_float2(o[mt][nb][2 * hh]     * inv_l,
                                                   o[mt][nb][2 * hh + 1] * inv_l);
            }
        }
}

// ---------------------------------------------------------------------------
extern "C" void kernel_launch(void* const* d_in, const int* in_sizes, int n_in,
                              void* d_out, int out_size) {
    const float* X  = (const float*)d_in[0];
    const float* Wq = (const float*)d_in[1];
    const float* Wk = (const float*)d_in[2];
    const float* Wv = (const float*)d_in[3];
    float* out = (float*)d_out;

    uint32_t* d_xh; cudaGetSymbolAddress((void**)&d_xh, g_xh);
    uint32_t* d_wh; cudaGetSymbolAddress((void**)&d_wh, g_wh);

    const int xn4 = MROWS * HID / 4;       // 1048576
    const int wn4 = HID * HID / 4;         // 262144
    to_half<<<xn4 / 256, 256>>>(X,  d_xh, xn4);
    to_half<<<wn4 / 256, 256>>>(Wq, d_wh,              wn4);
    to_half<<<wn4 / 256, 256>>>(Wk, d_wh + wn4 * 2,    wn4);
    to_half<<<wn4 / 256, 256>>>(Wv, d_wh + wn4 * 4,    wn4);
    rope_table<<<(SEQ * 32 + 255) / 256, 256>>>();
    qkv_gemm<<<dim3(HID / 128, MROWS / 128, 3), 256>>>();
    attn_kernel<<<dim3(SEQ / 128, NH * BATCH), 128>>>(out);
}

// round 16
// speedup vs baseline: 1.1495x; 1.0528x over previous
#include <cuda_runtime.h>
#include <cuda_fp16.h>
#include <math.h>
#include <stdint.h>

#define BATCH 2
#define SEQ   2048
#define NH    16
#define HD    64
#define HID   1024            // NH*HD
#define MROWS (BATCH*SEQ)     // 4096

// Scratch (no allocations allowed). q/k/v stored as half2 words in
// [B][H][S][64] layout: word index = ((b*16+h)*2048 + s)*32 + (d>>1).
__device__ uint32_t g_qh[MROWS * HID / 2];
__device__ uint32_t g_kh[MROWS * HID / 2];
__device__ uint32_t g_vh[MROWS * HID / 2];
// fp16 copies of the inputs (half2 words, row-major pairs along K)
__device__ uint32_t g_xh[MROWS * HID / 2];          // X  [4096][512]
__device__ uint32_t g_wh[3 * HID * HID / 2];        // Wq|Wk|Wv [1024][512] each
__device__ float g_cos[SEQ * 32];
__device__ float g_sin[SEQ * 32];

#define QSCALE (0.125f * 1.44269504088896f)   // 1/sqrt(64) * log2(e), folded into Q

__device__ __forceinline__ void mma_f16(float c[4], const uint32_t a[4],
                                        uint32_t b0, uint32_t b1) {
    asm volatile(
        "mma.sync.aligned.m16n8k16.row.col.f32.f16.f16.f32 "
        "{%0,%1,%2,%3},{%4,%5,%6,%7},{%8,%9},{%0,%1,%2,%3};"
        : "+f"(c[0]), "+f"(c[1]), "+f"(c[2]), "+f"(c[3])
        : "r"(a[0]), "r"(a[1]), "r"(a[2]), "r"(a[3]), "r"(b0), "r"(b1));
}

__device__ __forceinline__ uint32_t packh2(float lo, float hi) {
    __half2 h = __floats2half2_rn(lo, hi);
    return *(uint32_t*)&h;
}
__device__ __forceinline__ uint32_t h2u(__half2 h) { return *(uint32_t*)&h; }
__device__ __forceinline__ __half2 u2h(uint32_t u) { return *(__half2*)&u; }

// Bank-spread swizzle key for [row][pair] half2 layouts (32 words/row).
__device__ __forceinline__ int FSW(int d) { return ((d & 7) << 2) | ((d >> 3) & 3); }

__device__ __forceinline__ uint32_t smem_u32(const void* p) {
    uint32_t a;
    asm("{ .reg .u64 t; cvta.to.shared.u64 t, %1; cvt.u32.u64 %0, t; }"
        : "=r"(a) : "l"(p));
    return a;
}

#define CP_ASYNC16(dst, src) \
    asm volatile("cp.async.cg.shared.global [%0], [%1], 16;" :: "r"(dst), "l"(src))
#define CP_COMMIT() asm volatile("cp.async.commit_group;" ::: "memory")
#define CP_WAIT1()  asm volatile("cp.async.wait_group 1;" ::: "memory")

// ---------------------------------------------------------------------------
// fp32 -> fp16 bulk convert (X and W, once per launch)
// ---------------------------------------------------------------------------
__global__ void to_half(const float* __restrict__ src, uint32_t* __restrict__ dst,
                        int n4) {
    int i = blockIdx.x * blockDim.x + threadIdx.x;
    if (i >= n4) return;
    float4 v = ((const float4*)src)[i];
    ((uint2*)dst)[i] = make_uint2(packh2(v.x, v.y), packh2(v.z, v.w));
}

// ---------------------------------------------------------------------------
// RoPE tables — fp32 math, matching the reference's own fp32 computation.
// ---------------------------------------------------------------------------
__global__ void rope_table() {
    int idx = blockIdx.x * blockDim.x + threadIdx.x;
    if (idx >= SEQ * 32) return;
    int s = idx >> 5;
    int j = idx & 31;
    float inv = __expf((float)j * (-9.210340371976184f / 32.0f));
    float a = (float)s * inv;
    float sn, cs;
    sincosf(a, &sn, &cs);
    g_cos[idx] = cs;
    g_sin[idx] = sn;
}

// ---------------------------------------------------------------------------
// QKV projection, fp16 m16n8k16 with cp.async double-buffered staging.
// Y = X @ W^T, inputs pre-converted to half. Epilogue: RoPE (q,k) + per-head
// [B,H,S,64] half layout; Q scaled by QSCALE.
// Block tile 128x128, K-step 32, 2-stage pipeline. 8 warps in 4x2.
// ---------------------------------------------------------------------------
#define QPAD 20
__global__ __launch_bounds__(256)
void qkv_gemm() {
    __shared__ uint32_t As2[2][128 * QPAD];
    __shared__ uint32_t Bs2[2][128 * QPAD];

    const int z = blockIdx.z;
    const uint32_t* Ah = g_xh;
    const uint32_t* Bh = g_wh + (size_t)z * (HID * HID / 2);
    uint32_t* Yh       = (z == 0) ? g_qh : (z == 1) ? g_kh : g_vh;

    const int m0 = blockIdx.y * 128;
    const int n0 = blockIdx.x * 128;
    const int tid  = threadIdx.x;
    const int warp = tid >> 5;
    const int lane = tid & 31;
    const int g = lane >> 2;
    const int t = lane & 3;
    const int wm0 = (warp >> 1) * 32;   // 0,32,64,96
    const int wn0 = (warp & 1) * 64;    // 0,64

    // Per-thread cp.async slots: 512 16B groups per operand per stage,
    // 256 threads -> 2 slots each. slot idx: row = idx>>2, grp = idx&3.
    const int r0s = tid >> 2,          g0s = (tid & 3) * 4;          // words
    const int r1s = (tid + 256) >> 2,  g1s = ((tid + 256) & 3) * 4;
    const uint32_t sA = smem_u32(As2);
    const uint32_t sB = smem_u32(Bs2);
    const uint32_t stage_bytes = 128 * QPAD * 4;
    const uint32_t dA0 = (r0s * QPAD + g0s) * 4, dA1 = (r1s * QPAD + g1s) * 4;
    const uint32_t* srcA0 = Ah + (size_t)(m0 + r0s) * 512 + g0s;
    const uint32_t* srcA1 = Ah + (size_t)(m0 + r1s) * 512 + g1s;
    const uint32_t* srcB0 = Bh + (size_t)(n0 + r0s) * 512 + g0s;
    const uint32_t* srcB1 = Bh + (size_t)(n0 + r1s) * 512 + g1s;

    float acc[2][8][4];
#pragma unroll
    for (int mt = 0; mt < 2; mt++)
#pragma unroll
        for (int nt = 0; nt < 8; nt++)
#pragma unroll
            for (int e = 0; e < 4; e++) acc[mt][nt][e] = 0.0f;

    // Prologue: stage chunk 0 into buffer 0
    {
        CP_ASYNC16(sA + dA0, srcA0);
        CP_ASYNC16(sA + dA1, srcA1);
        CP_ASYNC16(sB + dA0, srcB0);
        CP_ASYNC16(sB + dA1, srcB1);
        CP_COMMIT();
    }

    for (int c = 0; c < 32; c++) {
        // Prefetch chunk c+1 into the other buffer
        if (c < 31) {
            uint32_t so = ((c + 1) & 1) * stage_bytes;
            int cw = (c + 1) * 16;            // word offset along K
            CP_ASYNC16(sA + so + dA0, srcA0 + cw);
            CP_ASYNC16(sA + so + dA1, srcA1 + cw);
            CP_ASYNC16(sB + so + dA0, srcB0 + cw);
            CP_ASYNC16(sB + so + dA1, srcB1 + cw);
        }
        CP_COMMIT();
        CP_WAIT1();              // chunk c resident
        __syncthreads();

        const uint32_t* bufA = As2[c & 1];
        const uint32_t* bufB = Bs2[c & 1];
#pragma unroll
        for (int kb = 0; kb < 2; kb++) {
            uint32_t a[2][4];
#pragma unroll
            for (int mt = 0; mt < 2; mt++) {
                int ra = (wm0 + mt * 16 + g) * QPAD;
                int rb = (wm0 + mt * 16 + 8 + g) * QPAD;
                a[mt][0] = bufA[ra + kb * 8 + t];
                a[mt][1] = bufA[rb + kb * 8 + t];
                a[mt][2] = bufA[ra + kb * 8 + 4 + t];
                a[mt][3] = bufA[rb + kb * 8 + 4 + t];
            }
#pragma unroll
            for (int nt = 0; nt < 8; nt++) {
                int rc = (wn0 + nt * 8 + g) * QPAD;
                uint32_t b0 = bufB[rc + kb * 8 + t];
                uint32_t b1 = bufB[rc + kb * 8 + 4 + t];
                mma_f16(acc[0][nt], a[0], b0, b1);
                mma_f16(acc[1][nt], a[1], b0, b1);
            }
        }
        __syncthreads();         // frag reads done before buffer reuse
    }

    // ---- Epilogue: RoPE (z<2) + fp16 + per-head layout ----
    const int head = (n0 + wn0) >> 6;   // this warp covers exactly one head
    const float sc = (z == 0) ? QSCALE : 1.0f;
#pragma unroll
    for (int mt = 0; mt < 2; mt++) {
        int r0 = m0 + wm0 + mt * 16 + g;        // rows r0 and r0+8
        int bq = r0 >> 11;
        int s0 = r0 & 2047;
        size_t base0 = ((size_t)(bq * 16 + head) * 2048 + s0) * 32;
        size_t base1 = base0 + 8 * 32;
        if (z < 2) {
#pragma unroll
            for (int nt = 0; nt < 4; nt++) {
                int j = nt * 8 + 2 * t;          // dim 0..30 (pairs with +32)
                float2 c0  = *(const float2*)&g_cos[s0 * 32 + j];
                float2 sn0 = *(const float2*)&g_sin[s0 * 32 + j];
                float2 c1  = *(const float2*)&g_cos[(s0 + 8) * 32 + j];
                float2 sn1 = *(const float2*)&g_sin[(s0 + 8) * 32 + j];
                float lo0 = acc[mt][nt][0],     lo1 = acc[mt][nt][1];
                float hi0 = acc[mt][nt + 4][0], hi1 = acc[mt][nt + 4][1];
                float lo2 = acc[mt][nt][2],     lo3 = acc[mt][nt][3];
                float hi2 = acc[mt][nt + 4][2], hi3 = acc[mt][nt + 4][3];
                int wl = nt * 4 + t;
                Yh[base0 + wl]      = packh2((lo0 * c0.x - hi0 * sn0.x) * sc,
                                             (lo1 * c0.y - hi1 * sn0.y) * sc);
                Yh[base0 + wl + 16] = packh2((hi0 * c0.x + lo0 * sn0.x) * sc,
                                             (hi1 * c0.y + lo1 * sn0.y) * sc);
                Yh[base1 + wl]      = packh2((lo2 * c1.x - hi2 * sn1.x) * sc,
                                             (lo3 * c1.y - hi3 * sn1.y) * sc);
                Yh[base1 + wl + 16] = packh2((hi2 * c1.x + lo2 * sn1.x) * sc,
                                             (hi3 * c1.y + lo3 * sn1.y) * sc);
            }
        } else {
#pragma unroll
            for (int nt = 0; nt < 8; nt++) {
                int wl = nt * 4 + t;
                Yh[base0 + wl] = packh2(acc[mt][nt][0], acc[mt][nt][1]);
                Yh[base1 + wl] = packh2(acc[mt][nt][2], acc[mt][nt][3]);
            }
        }
    }
}

// ---------------------------------------------------------------------------
// Flash attention, fp16 m16n8k16 (unchanged — known good).
// ---------------------------------------------------------------------------
__global__ __launch_bounds__(128)
void attn_kernel(float* __restrict__ out) {
    __shared__ uint32_t sh[4096];     // 16 KB
    uint32_t* Kh = sh;                // 2048 words
    uint32_t* Vh = sh + 2048;         // 2048 words

    const int tid  = threadIdx.x;
    const int warp = tid >> 5;
    const int lane = tid & 31;
    const int g = lane >> 2;
    const int t = lane & 3;
    const int h = blockIdx.y & (NH - 1);
    const int b = blockIdx.y >> 4;
    const int q0 = blockIdx.x * 128;

    const uint32_t* qh = g_qh + (size_t)(b * 16 + h) * 2048 * 32;
    const uint32_t* kh = g_kh + (size_t)(b * 16 + h) * 2048 * 32;
    const uint32_t* vh = g_vh + (size_t)(b * 16 + h) * 2048 * 32;

    // ---- Stage this warp's 32 Q rows (pure copy), grab frags ----
    uint32_t* Qs = sh + warp * 1024;  // 32 rows x 32 words
#pragma unroll
    for (int it = 0; it < 8; it++) {
        int idx = lane + it * 32;     // 0..255
        int r  = idx >> 3;
        int wq = (idx & 7) * 4;
        uint4 w = *(const uint4*)&qh[(size_t)(q0 + warp * 32 + r) * 32 + wq];
        int fr = FSW(r);
        Qs[r * 32 + ((wq + 0) ^ fr)] = w.x;
        Qs[r * 32 + ((wq + 1) ^ fr)] = w.y;
        Qs[r * 32 + ((wq + 2) ^ fr)] = w.z;
        Qs[r * 32 + ((wq + 3) ^ fr)] = w.w;
    }
    __syncwarp();
    uint32_t qa[2][4][4];
#pragma unroll
    for (int mt = 0; mt < 2; mt++) {
        int ra = mt * 16 + g, rb = mt * 16 + 8 + g;
        int fa = FSW(ra), fb = FSW(rb);
#pragma unroll
        for (int kb = 0; kb < 4; kb++) {
            qa[mt][kb][0] = Qs[ra * 32 + ((kb * 8 + t)     ^ fa)];
            qa[mt][kb][1] = Qs[rb * 32 + ((kb * 8 + t)     ^ fb)];
            qa[mt][kb][2] = Qs[ra * 32 + ((kb * 8 + t + 4) ^ fa)];
            qa[mt][kb][3] = Qs[rb * 32 + ((kb * 8 + t + 4) ^ fb)];
        }
    }

    float m_i[2][2], l_i[2][2];
    float o[2][8][4];
#pragma unroll
    for (int mt = 0; mt < 2; mt++) {
        m_i[mt][0] = m_i[mt][1] = -1e30f;
        l_i[mt][0] = l_i[mt][1] = 0.0f;
#pragma unroll
        for (int nb = 0; nb < 8; nb++)
#pragma unroll
            for (int e = 0; e < 4; e++) o[mt][nb][e] = 0.0f;
    }

    for (int k0 = 0; k0 < SEQ; k0 += 64) {
        __syncthreads();

        // ---- Stage K (pure copy, swizzled) ----
#pragma unroll
        for (int u = 0; u < 4; u++) {
            int idx = tid + u * 128;      // 0..511
            int r  = idx >> 3;            // key row 0..63
            int wq = (idx & 7) * 4;
            uint4 w = *(const uint4*)&kh[(size_t)(k0 + r) * 32 + wq];
            int fr = FSW(r);
            Kh[r * 32 + ((wq + 0) ^ fr)] = w.x;
            Kh[r * 32 + ((wq + 1) ^ fr)] = w.y;
            Kh[r * 32 + ((wq + 2) ^ fr)] = w.z;
            Kh[r * 32 + ((wq + 3) ^ fr)] = w.w;
        }
        // ---- Stage V transposed: Vh[dim][keypair] ----
#pragma unroll
        for (int u = 0; u < 4; u++) {
            int idx = tid + u * 128;      // 0..511
            int kp = idx >> 4;            // key pair 0..31
            int dq = idx & 15;            // dim quad: dims dq*4..+3
            uint2 a = *(const uint2*)&vh[(size_t)(k0 + 2 * kp) * 32 + dq * 2];
            uint2 c = *(const uint2*)&vh[(size_t)(k0 + 2 * kp + 1) * 32 + dq * 2];
            __half2 a0 = u2h(a.x), a1 = u2h(a.y);
            __half2 c0 = u2h(c.x), c1 = u2h(c.y);
            int d0 = dq * 4;
            Vh[(d0 + 0) * 32 + (kp ^ FSW(d0 + 0))] = h2u(__lows2half2(a0, c0));
            Vh[(d0 + 1) * 32 + (kp ^ FSW(d0 + 1))] = h2u(__highs2half2(a0, c0));
            Vh[(d0 + 2) * 32 + (kp ^ FSW(d0 + 2))] = h2u(__lows2half2(a1, c1));
            Vh[(d0 + 3) * 32 + (kp ^ FSW(d0 + 3))] = h2u(__highs2half2(a1, c1));
        }
        __syncthreads();

        // ---- S = Q @ K^T : 32x64 per warp (scores already in log2 domain) ----
        float s[2][8][4];
#pragma unroll
        for (int mt = 0; mt < 2; mt++)
#pragma unroll
            for (int nb = 0; nb < 8; nb++)
#pragma unroll
                for (int e = 0; e < 4; e++) s[mt][nb][e] = 0.0f;

#pragma unroll
        for (int kb = 0; kb < 4; kb++) {
#pragma unroll
            for (int nb = 0; nb < 8; nb++) {
                int key = nb * 8 + g;
                int fk = FSW(key);
                uint32_t b0 = Kh[key * 32 + ((kb * 8 + t)     ^ fk)];
                uint32_t b1 = Kh[key * 32 + ((kb * 8 + t + 4) ^ fk)];
                mma_f16(s[0][nb], qa[0][kb], b0, b1);
                mma_f16(s[1][nb], qa[1][kb], b0, b1);
            }
        }

        // ---- Online softmax (exp2 domain); pack P into fp16 A-frags ----
        uint32_t pa[2][4][4];
#pragma unroll
        for (int mt = 0; mt < 2; mt++) {
#pragma unroll
            for (int hh = 0; hh < 2; hh++) {
                const int e0 = hh * 2;
                float mx = -1e30f;
#pragma unroll
                for (int nb = 0; nb < 8; nb++)
                    mx = fmaxf(mx, fmaxf(s[mt][nb][e0], s[mt][nb][e0 + 1]));
                mx = fmaxf(mx, __shfl_xor_sync(0xffffffffu, mx, 1));
                mx = fmaxf(mx, __shfl_xor_sync(0xffffffffu, mx, 2));
                float mnew = fmaxf(m_i[mt][hh], mx);
                float corr = exp2f(m_i[mt][hh] - mnew);
                float rs = 0.0f;
#pragma unroll
                for (int nb = 0; nb < 8; nb++) {
                    float p0 = exp2f(s[mt][nb][e0]     - mnew);
                    float p1 = exp2f(s[mt][nb][e0 + 1] - mnew);
                    rs += p0 + p1;
                    s[mt][nb][e0]     = p0;
                    s[mt][nb][e0 + 1] = p1;
                }
                rs += __shfl_xor_sync(0xffffffffu, rs, 1);
                rs += __shfl_xor_sync(0xffffffffu, rs, 2);
                l_i[mt][hh] = l_i[mt][hh] * corr + rs;
                m_i[mt][hh] = mnew;
#pragma unroll
                for (int nb = 0; nb < 8; nb++) {
                    o[mt][nb][e0]     *= corr;
                    o[mt][nb][e0 + 1] *= corr;
                }
            }
#pragma unroll
            for (int kb = 0; kb < 4; kb++) {
                pa[mt][kb][0] = packh2(s[mt][2 * kb][0],     s[mt][2 * kb][1]);
                pa[mt][kb][1] = packh2(s[mt][2 * kb][2],     s[mt][2 * kb][3]);
                pa[mt][kb][2] = packh2(s[mt][2 * kb + 1][0], s[mt][2 * kb + 1][1]);
                pa[mt][kb][3] = packh2(s[mt][2 * kb + 1][2], s[mt][2 * kb + 1][3]);
            }
        }

        // ---- ctx += P @ V : 32x64 per warp ----
#pragma unroll
        for (int kb = 0; kb < 4; kb++) {
#pragma unroll
            for (int nb = 0; nb < 8; nb++) {
                int dim = nb * 8 + g;
                int fd = FSW(dim);
                uint32_t b0 = Vh[dim * 32 + ((kb * 8 + t)     ^ fd)];
                uint32_t b1 = Vh[dim * 32 + ((kb * 8 + t + 4) ^ fd)];
                mma_f16(o[0][nb], pa[0][kb], b0, b1);
                mma_f16(o[1][nb], pa[1][kb], b0, b1);
            }
        }
    }

    // ---- Normalize and write out[b, s, h*64 + d] ----
#pragma unroll
    for (int mt = 0; mt < 2; mt++)
#pragma unroll
        for (int hh = 0; hh < 2; hh++) {
            float inv_l = 1.0f / l_i[mt][hh];
            int row = q0 + warp * 32 + mt * 16 + g + 8 * hh;
#pragma unroll
            for (int nb = 0; nb < 8; nb++) {
                size_t base = (size_t)(b * SEQ + row) * HID + h * HD + nb * 8 + 2 * t;
                *(float2*)&out[base] = make_float2(o[mt][nb][2 * hh]     * inv_l,
                                                   o[mt][nb][2 * hh + 1] * inv_l);
            }
        }
}

// ---------------------------------------------------------------------------
extern "C" void kernel_launch(void* const* d_in, const int* in_sizes, int n_in,
                              void* d_out, int out_size) {
    const float* X  = (const float*)d_in[0];
    const float* Wq = (const float*)d_in[1];
    const float* Wk = (const float*)d_in[2];
    const float* Wv = (const float*)d_in[3];
    float* out = (float*)d_out;

    uint32_t* d_xh; cudaGetSymbolAddress((void**)&d_xh, g_xh);
    uint32_t* d_wh; cudaGetSymbolAddress((void**)&d_wh, g_wh);

    const int xn4 = MROWS * HID / 4;       // 1048576
    const int wn4 = HID * HID / 4;         // 262144
    to_half<<<xn4 / 256, 256>>>(X,  d_xh, xn4);
    to_half<<<wn4 / 256, 256>>>(Wq, d_wh,           wn4);
    to_half<<<wn4 / 256, 256>>>(Wk, d_wh + wn4 * 2, wn4);
    to_half<<<wn4 / 256, 256>>>(Wv, d_wh + wn4 * 4, wn4);
    rope_table<<<(SEQ * 32 + 255) / 256, 256>>>();
    qkv_gemm<<<dim3(HID / 128, MROWS / 128, 3), 256>>>();
    attn_kernel<<<dim3(SEQ / 128, NH * BATCH), 128>>>(out);
}